// round 4
// baseline (speedup 1.0000x reference)
#include <cuda_runtime.h>
#include <cstdint>

// Compressor: per-8x8-block DCT-II (C = M^T B M), per-block inf-norm,
// int8-bin quantization (round-half-even), outputs indices + biggest.
// x: 8192x8192 fp32. DCT matrix is compile-time constant (immediates -> FFMA-imm rt=1).

static constexpr int W_DIM  = 8192;
static constexpr int BLK    = 8;
static constexpr float RADIUS = 127.0f;
static constexpr float MAGIC  = 12582912.0f;   // 2^23 + 2^22: RNE rounder for |q| <= 127
static constexpr int CTA    = 128;
static constexpr int WARPS  = CTA / 32;

// Orthonormal DCT-II matrix M[element][frequency], float32-exact vs numpy float64->float32.
#define C0 0.35355339059327373f
#define C1 0.49039264020161522f
#define C2 0.46193976625564337f
#define C3 0.41573480615127262f
#define C4 0.35355339059327373f
#define C5 0.27778511650980109f
#define C6 0.19134171618254489f
#define C7 0.097545161008064127f
__device__ constexpr float DCT[8][8] = {
    { C0,  C1,  C2,  C3,  C4,  C5,  C6,  C7},
    { C0,  C3,  C6, -C7, -C4, -C1, -C2, -C5},
    { C0,  C5, -C6, -C1, -C4,  C7,  C2,  C3},
    { C0,  C7, -C2, -C5,  C4,  C3, -C6, -C1},
    { C0, -C7, -C2,  C5,  C4, -C3, -C6,  C1},
    { C0, -C5, -C6,  C1, -C4, -C7,  C2, -C3},
    { C0, -C3,  C6,  C7, -C4,  C1, -C2,  C5},
    { C0, -C1,  C2, -C3,  C4, -C5,  C6, -C7},
};

template <bool OUT_FLOAT>
__global__ __launch_bounds__(CTA, 6)
void dct_quant_kernel(const float* __restrict__ x,
                      void* __restrict__ out_indices,
                      float* __restrict__ out_biggest)
{
    __shared__ float4 stage[WARPS * 512];   // 8KB per warp = 32KB

    const int tid  = threadIdx.x;
    const int lane = tid & 31;
    const int wid  = tid >> 5;

    const int t  = blockIdx.x * CTA + tid;
    const int b1 = t >> 10;          // blocks_per_row = 1024
    const int b2 = t & 1023;

    // ---- Load 8x8 block, front-batched float4 streaming loads (MLP=16) ----
    const float* src = x + (size_t)(b1 * BLK) * W_DIM + (size_t)b2 * BLK;
    float A[8][8];   // in-place: B -> D -> C
#pragma unroll
    for (int e = 0; e < 8; e++) {
        const float4 v0 = __ldcs(reinterpret_cast<const float4*>(src + (size_t)e * W_DIM));
        const float4 v1 = __ldcs(reinterpret_cast<const float4*>(src + (size_t)e * W_DIM + 4));
        A[e][0] = v0.x; A[e][1] = v0.y; A[e][2] = v0.z; A[e][3] = v0.w;
        A[e][4] = v1.x; A[e][5] = v1.y; A[e][6] = v1.z; A[e][7] = v1.w;
    }

    // ---- Stage 1 (in-place, column-wise): D[g][f] = sum_e M[e][g] * B[e][f] ----
    // DCT[][] constants fold into FFMA immediates (rt=1).
#pragma unroll
    for (int f = 0; f < 8; f++) {
        float col[8];
#pragma unroll
        for (int g = 0; g < 8; g++) col[g] = 0.0f;
#pragma unroll
        for (int e = 0; e < 8; e++) {
            const float b = A[e][f];
#pragma unroll
            for (int g = 0; g < 8; g++)
                col[g] = fmaf(DCT[e][g], b, col[g]);
        }
#pragma unroll
        for (int g = 0; g < 8; g++) A[g][f] = col[g];
    }

    // ---- Stage 2 (in-place, row-wise): C[g][h] = sum_f D[g][f] * M[f][h]; inf-norm ----
    float maxv = 0.0f;
#pragma unroll
    for (int g = 0; g < 8; g++) {
        float row[8];
#pragma unroll
        for (int h = 0; h < 8; h++) row[h] = 0.0f;
#pragma unroll
        for (int f = 0; f < 8; f++) {
            const float d = A[g][f];
#pragma unroll
            for (int h = 0; h < 8; h++)
                row[h] = fmaf(d, DCT[f][h], row[h]);
        }
#pragma unroll
        for (int h = 0; h < 8; h++) {
            A[g][h] = row[h];
            maxv = fmaxf(maxv, fabsf(row[h]));
        }
    }

    const float scale = RADIUS / maxv;

    // RNE quantize without F2I/I2F: (rn(v*scale) + MAGIC) - MAGIC.
    // Bit-identical to (float)__float2int_rn(v*scale) for |q| <= 127.
#define QUANT(v) (__fadd_rn(__fadd_rn(__fmul_rn((v), scale), MAGIC), -MAGIC))

    if (OUT_FLOAT) {
        // Stage quantized floats in per-warp swizzled SMEM, then dense 8KB warp stores.
        float4* wbuf = stage + wid * 512;
#pragma unroll
        for (int j = 0; j < 16; j++) {
            const int g  = j >> 1;
            const int hb = (j & 1) * 4;
            float4 v;
            v.x = QUANT(A[g][hb + 0]);
            v.y = QUANT(A[g][hb + 1]);
            v.z = QUANT(A[g][hb + 2]);
            v.w = QUANT(A[g][hb + 3]);
            wbuf[lane * 16 + (j ^ (lane & 7))] = v;
        }
        __syncwarp();

        const int warp_first_block = blockIdx.x * CTA + wid * 32;
        float4* gout = reinterpret_cast<float4*>(
            reinterpret_cast<float*>(out_indices) + (size_t)warp_first_block * 64);
#pragma unroll
        for (int k = 0; k < 16; k++) {
            const int m    = k * 32 + lane;
            const int tsrc = m >> 4;
            const int j    = m & 15;
            const float4 v = wbuf[tsrc * 16 + (j ^ (tsrc & 7))];
            __stcs(gout + m, v);
        }
    } else {
        uint32_t words[16];
#pragma unroll
        for (int i = 0; i < 16; i++) {
            const int g = i >> 1;
            const int hb = (i & 1) * 4;
            uint32_t w = 0;
#pragma unroll
            for (int j = 0; j < 4; j++) {
                const int q = __float2int_rn(A[g][hb + j] * scale);
                w |= (uint32_t)(q & 0xFF) << (8 * j);
            }
            words[i] = w;
        }
        uint4* outp = reinterpret_cast<uint4*>(
            reinterpret_cast<int8_t*>(out_indices) + (size_t)t * 64);
#pragma unroll
        for (int i = 0; i < 4; i++)
            __stcs(outp + i, make_uint4(words[4*i], words[4*i+1], words[4*i+2], words[4*i+3]));
    }
#undef QUANT

    __stcs(out_biggest + t, maxv);
}

extern "C" void kernel_launch(void* const* d_in, const int* in_sizes, int n_in,
                              void* d_out, int out_size)
{
    const float* x = (const float*)d_in[0];
    // d_in[1] (dct) is a fixed orthonormal DCT-II matrix; baked in as immediates.

    const int n        = in_sizes[0];          // 67108864
    const int nblocks  = n / 64;               // 1048576
    const int grid     = nblocks / CTA;        // 8192

    if (out_size == n + nblocks) {
        float* outF = (float*)d_out;
        dct_quant_kernel<true><<<grid, CTA>>>(x, (void*)outF, outF + n);
    } else {
        int8_t* idx = (int8_t*)d_out;
        float*  big = (float*)((char*)d_out + (size_t)n);
        dct_quant_kernel<false><<<grid, CTA>>>(x, (void*)idx, big);
    }
}

// round 5
// speedup vs baseline: 1.3340x; 1.3340x over previous
#include <cuda_runtime.h>
#include <cstdint>

// Compressor: per-8x8-block DCT-II (C = M^T B M), per-block inf-norm,
// int8-bin quantization (round-half-even). Two threads cooperate per block
// via the DCT even/odd butterfly: lane h=0 owns rows 0-3 -> even freqs,
// lane h=1 owns rows 4-7 -> odd freqs.

static constexpr int W_DIM  = 8192;
static constexpr float RADIUS = 127.0f;
static constexpr float MAGIC  = 12582912.0f;   // 2^23+2^22: RNE rounder, |q|<=127
static constexpr int CTA    = 128;
static constexpr int WARPS  = CTA / 32;

#define C0 0.35355339059327373f
#define C1 0.49039264020161522f
#define C2 0.46193976625564337f
#define C3 0.41573480615127262f
#define C4 0.35355339059327373f
#define C5 0.27778511650980109f
#define C6 0.19134171618254489f
#define C7 0.097545161008064127f

__global__ __launch_bounds__(CTA, 8)
void dct_quant_pair_kernel(const float* __restrict__ x,
                           float* __restrict__ out_indices,
                           float* __restrict__ out_biggest)
{
    __shared__ float4 stage[WARPS * 256];   // 4KB per warp = 16KB

    const int tid  = threadIdx.x;
    const int lane = tid & 31;
    const int wid  = tid >> 5;
    const int h    = lane >> 4;    // 0: rows 0-3 / even freqs, 1: rows 4-7 / odd freqs
    const int b    = lane & 15;    // block within warp

    const int warpBase = blockIdx.x * (WARPS * 16) + wid * 16;
    const int t  = warpBase + b;   // block id
    const int b1 = t >> 10;        // 1024 blocks per row
    const int b2 = t & 1023;

    // ---- Load my 4 rows (8 front-batched float4 streaming loads) ----
    const float* src = x + (size_t)(b1 * 8 + h * 4) * W_DIM + (size_t)b2 * 8;
    float A[4][8];
#pragma unroll
    for (int r = 0; r < 4; r++) {
        const float4 v0 = __ldcs(reinterpret_cast<const float4*>(src + (size_t)r * W_DIM));
        const float4 v1 = __ldcs(reinterpret_cast<const float4*>(src + (size_t)r * W_DIM + 4));
        A[r][0] = v0.x; A[r][1] = v0.y; A[r][2] = v0.z; A[r][3] = v0.w;
        A[r][4] = v1.x; A[r][5] = v1.y; A[r][6] = v1.z; A[r][7] = v1.w;
    }

    const float sgn = h ? -1.0f : 1.0f;

    // ---- Stage 1 per column f: exchange + butterfly + 4-pt transform, in place ----
    // Round i: h=0 sends B[i] (global row i), h=1 sends B[3-i] (global row 7-i).
    //   h=0: s[i] = B[i] + recv      (global B[i] + B[7-i])
    //   h=1: d[i] = recv - B[3-i]    (global B[i] - B[7-i])
    // Common form: o[i] = recv + sgn * a, a = h ? B[3-i] : B[i]  (= value sent).
#pragma unroll
    for (int f = 0; f < 8; f++) {
        float o[4];
#pragma unroll
        for (int i = 0; i < 4; i++) {
            const float a = h ? A[3 - i][f] : A[i][f];
            const float r = __shfl_xor_sync(0xffffffffu, a, 16);
            o[i] = fmaf(sgn, a, r);
        }
        if (h == 0) {
            // even freqs {0,2,4,6} from s = o
            const float t0 = o[0] + o[3], t1 = o[1] + o[2];
            const float u0 = o[0] - o[3], u1 = o[1] - o[2];
            A[0][f] = C0 * (t0 + t1);                     // F0
            A[1][f] = fmaf(C2, u0,  C6 * u1);             // F2
            A[2][f] = C4 * (t0 - t1);                     // F4
            A[3][f] = fmaf(C6, u0, -(C2 * u1));           // F6
        } else {
            // odd freqs {1,3,5,7} from d = o
            A[0][f] = fmaf(C7, o[3], fmaf( C5, o[2], fmaf( C3, o[1],  C1 * o[0]))); // F1
            A[1][f] = fmaf(-C5, o[3], fmaf(-C1, o[2], fmaf(-C7, o[1],  C3 * o[0]))); // F3
            A[2][f] = fmaf(C3, o[3], fmaf( C7, o[2], fmaf(-C1, o[1],  C5 * o[0]))); // F5
            A[3][f] = fmaf(-C1, o[3], fmaf( C3, o[2], fmaf(-C5, o[1],  C7 * o[0]))); // F7
        }
    }

    // ---- Stage 2: thread-local row butterfly on my 4 D-rows; track inf-norm ----
    float maxv = 0.0f;
#pragma unroll
    for (int l = 0; l < 4; l++) {
        const float v0=A[l][0], v1=A[l][1], v2=A[l][2], v3=A[l][3];
        const float v4=A[l][4], v5=A[l][5], v6=A[l][6], v7=A[l][7];
        const float s0=v0+v7, s1=v1+v6, s2=v2+v5, s3=v3+v4;
        const float d0=v0-v7, d1=v1-v6, d2=v2-v5, d3=v3-v4;
        const float t0=s0+s3, t1=s1+s2, u0=s0-s3, u1=s1-s2;
        A[l][0] = C0 * (t0 + t1);
        A[l][4] = C4 * (t0 - t1);
        A[l][2] = fmaf(C2, u0,  C6 * u1);
        A[l][6] = fmaf(C6, u0, -(C2 * u1));
        A[l][1] = fmaf(C7, d3, fmaf( C5, d2, fmaf( C3, d1,  C1 * d0)));
        A[l][3] = fmaf(-C5, d3, fmaf(-C1, d2, fmaf(-C7, d1,  C3 * d0)));
        A[l][5] = fmaf(C3, d3, fmaf( C7, d2, fmaf(-C1, d1,  C5 * d0)));
        A[l][7] = fmaf(-C1, d3, fmaf( C3, d2, fmaf(-C5, d1,  C7 * d0)));
#pragma unroll
        for (int j = 0; j < 8; j++) maxv = fmaxf(maxv, fabsf(A[l][j]));
    }

    // Pair max -> per-block inf-norm and scale
    maxv = fmaxf(maxv, __shfl_xor_sync(0xffffffffu, maxv, 16));
    const float scale = RADIUS / maxv;

    // RNE quantize without converts: (rn(v*scale)+MAGIC)-MAGIC, exact for |q|<=127
#define QUANT(v) (__fadd_rn(__fadd_rn(__fmul_rn((v), scale), MAGIC), -MAGIC))

    // ---- Stage quantized rows into per-warp swizzled SMEM ----
    // Block b occupies float4 slots [b*16, b*16+16). Local row l is global
    // freq row g = 2l+h -> float4 slot j = 4l + 2h + q (q=0,1). Swizzle j^(b&7).
    float4* wbuf = stage + wid * 256;
#pragma unroll
    for (int l = 0; l < 4; l++) {
#pragma unroll
        for (int q = 0; q < 2; q++) {
            const int j = 4 * l + 2 * h + q;
            float4 v;
            v.x = QUANT(A[l][4*q + 0]);
            v.y = QUANT(A[l][4*q + 1]);
            v.z = QUANT(A[l][4*q + 2]);
            v.w = QUANT(A[l][4*q + 3]);
            wbuf[b * 16 + (j ^ (b & 7))] = v;
        }
    }
#undef QUANT
    __syncwarp();

    // ---- Dense 4KB warp store (8 STG.128 per lane, fully coalesced) ----
    float4* gout = reinterpret_cast<float4*>(out_indices) + (size_t)warpBase * 16;
#pragma unroll
    for (int k = 0; k < 8; k++) {
        const int p  = k * 32 + lane;
        const int bb = p >> 4;
        const int jj = p & 15;
        __stcs(gout + p, wbuf[bb * 16 + (jj ^ (bb & 7))]);
    }

    if (h == 0) __stcs(out_biggest + t, maxv);
}

// ---- Fallback (byte-packed int8 output layout): simple 1-thread-per-block ----
__global__ __launch_bounds__(128)
void dct_quant_i8_kernel(const float* __restrict__ x,
                         int8_t* __restrict__ out_indices,
                         float* __restrict__ out_biggest)
{
    const int t  = blockIdx.x * 128 + threadIdx.x;
    const int b1 = t >> 10;
    const int b2 = t & 1023;
    const float* src = x + (size_t)(b1 * 8) * W_DIM + (size_t)b2 * 8;
    float A[8][8];
#pragma unroll
    for (int e = 0; e < 8; e++) {
        const float4 v0 = __ldcs(reinterpret_cast<const float4*>(src + (size_t)e * W_DIM));
        const float4 v1 = __ldcs(reinterpret_cast<const float4*>(src + (size_t)e * W_DIM + 4));
        A[e][0]=v0.x; A[e][1]=v0.y; A[e][2]=v0.z; A[e][3]=v0.w;
        A[e][4]=v1.x; A[e][5]=v1.y; A[e][6]=v1.z; A[e][7]=v1.w;
    }
    const float M[8] = {C0,C1,C2,C3,C4,C5,C6,C7};
    // full DCT matrix from symmetry
    float Mx[8][8];
#pragma unroll
    for (int e = 0; e < 8; e++) {
        Mx[e][0]=C0;
#pragma unroll
        for (int g = 1; g < 8; g++) {
            // M[e][g] = sqrt(2/8) cos(pi(2e+1)g/16); use recurrences? just table:
            Mx[e][g] = 0.0f;
        }
    }
    // direct constant table
    const float T[8][8] = {
        { C0,  C1,  C2,  C3,  C4,  C5,  C6,  C7},
        { C0,  C3,  C6, -C7, -C4, -C1, -C2, -C5},
        { C0,  C5, -C6, -C1, -C4,  C7,  C2,  C3},
        { C0,  C7, -C2, -C5,  C4,  C3, -C6, -C1},
        { C0, -C7, -C2,  C5,  C4, -C3, -C6,  C1},
        { C0, -C5, -C6,  C1, -C4, -C7,  C2, -C3},
        { C0, -C3,  C6,  C7, -C4,  C1, -C2,  C5},
        { C0, -C1,  C2, -C3,  C4, -C5,  C6, -C7},
    };
    (void)M; (void)Mx;
#pragma unroll
    for (int f = 0; f < 8; f++) {
        float col[8];
#pragma unroll
        for (int g = 0; g < 8; g++) col[g] = 0.0f;
#pragma unroll
        for (int e = 0; e < 8; e++)
#pragma unroll
            for (int g = 0; g < 8; g++) col[g] = fmaf(T[e][g], A[e][f], col[g]);
#pragma unroll
        for (int g = 0; g < 8; g++) A[g][f] = col[g];
    }
    float maxv = 0.0f;
#pragma unroll
    for (int g = 0; g < 8; g++) {
        float row[8];
#pragma unroll
        for (int hh = 0; hh < 8; hh++) row[hh] = 0.0f;
#pragma unroll
        for (int f = 0; f < 8; f++)
#pragma unroll
            for (int hh = 0; hh < 8; hh++) row[hh] = fmaf(A[g][f], T[f][hh], row[hh]);
#pragma unroll
        for (int hh = 0; hh < 8; hh++) { A[g][hh] = row[hh]; maxv = fmaxf(maxv, fabsf(row[hh])); }
    }
    const float scale = RADIUS / maxv;
    uint32_t words[16];
#pragma unroll
    for (int i = 0; i < 16; i++) {
        const int g = i >> 1, hb = (i & 1) * 4;
        uint32_t w = 0;
#pragma unroll
        for (int j = 0; j < 4; j++) {
            const int q = __float2int_rn(A[g][hb + j] * scale);
            w |= (uint32_t)(q & 0xFF) << (8 * j);
        }
        words[i] = w;
    }
    uint4* outp = reinterpret_cast<uint4*>(out_indices + (size_t)t * 64);
#pragma unroll
    for (int i = 0; i < 4; i++)
        __stcs(outp + i, make_uint4(words[4*i], words[4*i+1], words[4*i+2], words[4*i+3]));
    __stcs(out_biggest + t, maxv);
}

extern "C" void kernel_launch(void* const* d_in, const int* in_sizes, int n_in,
                              void* d_out, int out_size)
{
    const float* x = (const float*)d_in[0];
    // d_in[1] (dct) is the fixed orthonormal DCT-II matrix; baked in as constants.

    const int n       = in_sizes[0];        // 67108864
    const int nblocks = n / 64;             // 1048576

    if (out_size == n + nblocks) {
        float* outF = (float*)d_out;
        const int grid = (nblocks * 2) / CTA;   // 16384, 2 threads per block
        dct_quant_pair_kernel<<<grid, CTA>>>(x, outF, outF + n);
    } else {
        int8_t* idx = (int8_t*)d_out;
        float*  big = (float*)((char*)d_out + (size_t)n);
        dct_quant_i8_kernel<<<nblocks / 128, 128>>>(x, idx, big);
    }
}

// round 6
// speedup vs baseline: 1.3428x; 1.0066x over previous
#include <cuda_runtime.h>
#include <cstdint>

// Compressor: per-8x8-block DCT-II (C = M^T B M), per-block inf-norm,
// int8-bin quantization (round-half-even). FOUR lanes cooperate per block:
// lane role c owns output/input columns {2c, 2c+1}. Stage-1 column DCT is
// thread-local; stage-2 row DCT uses a 3-round xor-shuffle butterfly.

static constexpr int W_DIM  = 8192;
static constexpr float RADIUS = 127.0f;
static constexpr float MAGIC  = 12582912.0f;   // 2^23+2^22: RNE rounder, |q|<=127
static constexpr int CTA    = 128;
static constexpr int WARPS  = CTA / 32;

#define C0 0.35355339059327373f
#define C1 0.49039264020161522f
#define C2 0.46193976625564337f
#define C3 0.41573480615127262f
#define C4 0.35355339059327373f
#define C5 0.27778511650980109f
#define C6 0.19134171618254489f
#define C7 0.097545161008064127f

// Round-2 coefficient tables over operand vector (o0, o1, q0, q1), per lane role c.
// Lane c computes Fa (kept) and Fb (sent in round 3).
//  c=0: o=(s0,s1) q=(s2,s3):  Fa=F0, Fb=F4
//  c=1: o=(s2,s3) q=(s0,s1):  Fa=F2, Fb=F6
//  c=2: o=(d2,d3) q=(d0,d1):  Fa=F5, Fb=F1
//  c=3: o=(d0,d1) q=(d2,d3):  Fa=F7, Fb=F3
__constant__ float KA[4][4] = {
    { C0,  C0,  C0,  C0},
    {-C6, -C2,  C2,  C6},
    { C7,  C3,  C5, -C1},
    { C7, -C5,  C3, -C1},
};
__constant__ float KB[4][4] = {
    { C4, -C4, -C4,  C4},
    { C2, -C6,  C6, -C2},
    { C5,  C7,  C1,  C3},
    { C3, -C7, -C1, -C5},
};

__global__ __launch_bounds__(CTA, 10)
void dct_quant_quad_kernel(const float* __restrict__ x,
                           float* __restrict__ out_indices,
                           float* __restrict__ out_biggest)
{
    __shared__ float2 stage[WARPS * 256];   // 2KB per warp = 8KB

    const int tid  = threadIdx.x;
    const int lane = tid & 31;
    const int wid  = tid >> 5;
    const int b    = lane >> 2;    // block within warp (0..7)
    const int c    = lane & 3;     // column-pair role: owns cols {2c, 2c+1}
    const bool evn = (c < 2);      // s-side lanes

    const int warpBase = blockIdx.x * (WARPS * 8) + wid * 8;
    const int t  = warpBase + b;   // block id
    const int b1 = t >> 10;        // 1024 blocks per row
    const int b2 = t & 1023;

    // ---- Load cols {2c,2c+1} x 8 rows: 8 float2 loads, warp-dense 256B/row ----
    const float* src = x + (size_t)(b1 * 8) * W_DIM + (size_t)b2 * 8 + c * 2;
    float A[8][2];
#pragma unroll
    for (int r = 0; r < 8; r++) {
        const float2 v = __ldcs(reinterpret_cast<const float2*>(src + (size_t)r * W_DIM));
        A[r][0] = v.x; A[r][1] = v.y;
    }

    // ---- Stage 1: thread-local 8-point DCT down each owned column ----
#pragma unroll
    for (int j = 0; j < 2; j++) {
        const float a0=A[0][j], a1=A[1][j], a2=A[2][j], a3=A[3][j];
        const float a4=A[4][j], a5=A[5][j], a6=A[6][j], a7=A[7][j];
        const float s0=a0+a7, s1=a1+a6, s2=a2+a5, s3=a3+a4;
        const float d0=a0-a7, d1=a1-a6, d2=a2-a5, d3=a3-a4;
        const float t0=s0+s3, t1=s1+s2, u0=s0-s3, u1=s1-s2;
        A[0][j] = C0 * (t0 + t1);
        A[4][j] = C4 * (t0 - t1);
        A[2][j] = fmaf(C2, u0,  C6 * u1);
        A[6][j] = fmaf(C6, u0, -(C2 * u1));
        A[1][j] = fmaf(C7, d3, fmaf( C5, d2, fmaf( C3, d1,  C1 * d0)));
        A[3][j] = fmaf(-C5, d3, fmaf(-C1, d2, fmaf(-C7, d1,  C3 * d0)));
        A[5][j] = fmaf(C3, d3, fmaf( C7, d2, fmaf(-C1, d1,  C5 * d0)));
        A[7][j] = fmaf(-C1, d3, fmaf( C3, d2, fmaf(-C5, d1,  C7 * d0)));
    }

    // Round-2 coefficients for this lane role (4 distinct const addrs, loaded once)
    const float ka0 = KA[c][0], ka1 = KA[c][1], ka2 = KA[c][2], ka3 = KA[c][3];
    const float kb0 = KB[c][0], kb1 = KB[c][1], kb2 = KB[c][2], kb3 = KB[c][3];

    // ---- Stage 2: distributed row DCT, 5 shuffles per row ----
    float maxv = 0.0f;
#pragma unroll
    for (int g = 0; g < 8; g++) {
        const float m0 = A[g][0], m1 = A[g][1];
        // Round 1 (xor3): partner holds cols {2(3-c), 2(3-c)+1}
        const float p0 = __shfl_xor_sync(0xffffffffu, m0, 3);
        const float p1 = __shfl_xor_sync(0xffffffffu, m1, 3);
        //  c<2: o = (s[2c], s[2c+1]);  c>=2: o = (d[*], d[*])
        const float o0 = evn ? (m0 + p1) : (p0 - m1);
        const float o1 = evn ? (m1 + p0) : (p1 - m0);
        // Round 2 (xor1): get the other half of my s/d group
        const float q0 = __shfl_xor_sync(0xffffffffu, o0, 1);
        const float q1 = __shfl_xor_sync(0xffffffffu, o1, 1);
        const float Fa = fmaf(ka3, q1, fmaf(ka2, q0, fmaf(ka1, o1, ka0 * o0)));
        const float Fb = fmaf(kb3, q1, fmaf(kb2, q0, fmaf(kb1, o1, kb0 * o0)));
        // Round 3 (xor2): swap Fb across the even/odd groups
        const float rec = __shfl_xor_sync(0xffffffffu, Fb, 2);
        A[g][0] = evn ? Fa  : rec;   // col 2c
        A[g][1] = evn ? rec : Fa;    // col 2c+1
        maxv = fmaxf(maxv, fmaxf(fabsf(A[g][0]), fabsf(A[g][1])));
    }

    // Per-block inf-norm over the quad (lanes 4b..4b+3)
    maxv = fmaxf(maxv, __shfl_xor_sync(0xffffffffu, maxv, 1));
    maxv = fmaxf(maxv, __shfl_xor_sync(0xffffffffu, maxv, 2));
    const float scale = RADIUS / maxv;

    // RNE quantize without converts: (rn(v*scale)+MAGIC)-MAGIC, exact for |q|<=127
#define QUANT(v) (__fadd_rn(__fadd_rn(__fmul_rn((v), scale), MAGIC), -MAGIC))

    // ---- Stage quantized float2s into per-warp SMEM (additive swizzle) ----
    // Block b, row g, role c -> float2 slot (g*4+c + 4*b) & 31 within block region.
    float2* wbuf = stage + wid * 256;
#pragma unroll
    for (int g = 0; g < 8; g++) {
        float2 v;
        v.x = QUANT(A[g][0]);
        v.y = QUANT(A[g][1]);
        wbuf[b * 32 + ((g * 4 + c + 4 * b) & 31)] = v;
    }
#undef QUANT
    __syncwarp();

    // ---- Dense 2KB warp store: 4 STG.128 per lane, fully coalesced ----
    const float4* wbuf4 = reinterpret_cast<const float4*>(wbuf);
    float4* gout = reinterpret_cast<float4*>(out_indices) + (size_t)warpBase * 16;
#pragma unroll
    for (int k = 0; k < 4; k++) {
        const int p  = k * 32 + lane;
        const int bb = p >> 4;
        const int f4 = p & 15;
        __stcs(gout + p, wbuf4[bb * 16 + ((f4 + 2 * bb) & 15)]);
    }

    if (c == 0) __stcs(out_biggest + t, maxv);
}

// ---- Fallback (byte-packed int8 output layout) ----
__global__ __launch_bounds__(128)
void dct_quant_i8_kernel(const float* __restrict__ x,
                         int8_t* __restrict__ out_indices,
                         float* __restrict__ out_biggest)
{
    const int t  = blockIdx.x * 128 + threadIdx.x;
    const int b1 = t >> 10;
    const int b2 = t & 1023;
    const float* src = x + (size_t)(b1 * 8) * W_DIM + (size_t)b2 * 8;
    float A[8][8];
#pragma unroll
    for (int e = 0; e < 8; e++) {
        const float4 v0 = __ldcs(reinterpret_cast<const float4*>(src + (size_t)e * W_DIM));
        const float4 v1 = __ldcs(reinterpret_cast<const float4*>(src + (size_t)e * W_DIM + 4));
        A[e][0]=v0.x; A[e][1]=v0.y; A[e][2]=v0.z; A[e][3]=v0.w;
        A[e][4]=v1.x; A[e][5]=v1.y; A[e][6]=v1.z; A[e][7]=v1.w;
    }
    const float T[8][8] = {
        { C0,  C1,  C2,  C3,  C4,  C5,  C6,  C7},
        { C0,  C3,  C6, -C7, -C4, -C1, -C2, -C5},
        { C0,  C5, -C6, -C1, -C4,  C7,  C2,  C3},
        { C0,  C7, -C2, -C5,  C4,  C3, -C6, -C1},
        { C0, -C7, -C2,  C5,  C4, -C3, -C6,  C1},
        { C0, -C5, -C6,  C1, -C4, -C7,  C2, -C3},
        { C0, -C3,  C6,  C7, -C4,  C1, -C2,  C5},
        { C0, -C1,  C2, -C3,  C4, -C5,  C6, -C7},
    };
#pragma unroll
    for (int f = 0; f < 8; f++) {
        float col[8];
#pragma unroll
        for (int g = 0; g < 8; g++) col[g] = 0.0f;
#pragma unroll
        for (int e = 0; e < 8; e++)
#pragma unroll
            for (int g = 0; g < 8; g++) col[g] = fmaf(T[e][g], A[e][f], col[g]);
#pragma unroll
        for (int g = 0; g < 8; g++) A[g][f] = col[g];
    }
    float maxv = 0.0f;
#pragma unroll
    for (int g = 0; g < 8; g++) {
        float row[8];
#pragma unroll
        for (int hh = 0; hh < 8; hh++) row[hh] = 0.0f;
#pragma unroll
        for (int f = 0; f < 8; f++)
#pragma unroll
            for (int hh = 0; hh < 8; hh++) row[hh] = fmaf(A[g][f], T[f][hh], row[hh]);
#pragma unroll
        for (int hh = 0; hh < 8; hh++) { A[g][hh] = row[hh]; maxv = fmaxf(maxv, fabsf(row[hh])); }
    }
    const float scale = RADIUS / maxv;
    uint32_t words[16];
#pragma unroll
    for (int i = 0; i < 16; i++) {
        const int g = i >> 1, hb = (i & 1) * 4;
        uint32_t w = 0;
#pragma unroll
        for (int j = 0; j < 4; j++) {
            const int q = __float2int_rn(A[g][hb + j] * scale);
            w |= (uint32_t)(q & 0xFF) << (8 * j);
        }
        words[i] = w;
    }
    uint4* outp = reinterpret_cast<uint4*>(out_indices + (size_t)t * 64);
#pragma unroll
    for (int i = 0; i < 4; i++)
        __stcs(outp + i, make_uint4(words[4*i], words[4*i+1], words[4*i+2], words[4*i+3]));
    __stcs(out_biggest + t, maxv);
}

extern "C" void kernel_launch(void* const* d_in, const int* in_sizes, int n_in,
                              void* d_out, int out_size)
{
    const float* x = (const float*)d_in[0];
    // d_in[1] (dct) is the fixed orthonormal DCT-II matrix; baked in as constants.

    const int n       = in_sizes[0];        // 67108864
    const int nblocks = n / 64;             // 1048576

    if (out_size == n + nblocks) {
        float* outF = (float*)d_out;
        const int grid = (nblocks * 4) / CTA;   // 32768, 4 lanes per block
        dct_quant_quad_kernel<<<grid, CTA>>>(x, outF, outF + n);
    } else {
        int8_t* idx = (int8_t*)d_out;
        float*  big = (float*)((char*)d_out + (size_t)n);
        dct_quant_i8_kernel<<<nblocks / 128, 128>>>(x, idx, big);
    }
}